// round 6
// baseline (speedup 1.0000x reference)
#include <cuda_runtime.h>
#include <math.h>

#define S_ 512
#define L_ 128

// ---- packed f32x2 helpers ----
__device__ __forceinline__ float2 ffma2(float2 a, float2 b, float2 c) {
    unsigned long long ua = *reinterpret_cast<unsigned long long*>(&a);
    unsigned long long ub = *reinterpret_cast<unsigned long long*>(&b);
    unsigned long long uc = *reinterpret_cast<unsigned long long*>(&c);
    unsigned long long ud;
    asm("fma.rn.f32x2 %0, %1, %2, %3;" : "=l"(ud) : "l"(ua), "l"(ub), "l"(uc));
    return *reinterpret_cast<float2*>(&ud);
}
__device__ __forceinline__ float2 dup2(float a) {
    unsigned long long u;
    asm("mov.b64 %0, {%1, %1};" : "=l"(u) : "f"(a));
    return *reinterpret_cast<float2*>(&u);
}

// ---- scratch ----
__device__ __align__(16) float g_xwork[(size_t)4*64*128*128];
__device__ __align__(16) float g_u[(size_t)S_*L_*64];
__device__ __align__(16) float g_zx[2][(size_t)S_*L_*384];   // z | raw xBC
__device__ __align__(16) float g_dt[2][(size_t)S_*L_*4];     // {dt0,dt1,ldA0,ldA1}
__device__ __align__(16) float g_gbuf[(size_t)S_*L_*256];
__device__ __align__(16) float g_wc[64*256];

// ============================================================
// LayerNorm over channels + layout to (seq, pos, ch)
// ============================================================
__global__ void ln_kernel(const float* __restrict__ x_ext,
                          const float* __restrict__ lnw, const float* __restrict__ lnb,
                          int stage)
{
    __shared__ float tile[64][133];
    __shared__ float msh[128], rsh[128], wsh[64], bsh[64];
    const float* xin = stage ? g_xwork : x_ext;
    int bt = blockIdx.x, b = bt >> 7, t = bt & 127;
    int tid = threadIdx.x;
    if (tid < 64) { wsh[tid] = lnw[tid]; bsh[tid] = lnb[tid]; }
    const float* xb = xin + ((size_t)b*64*128 + t)*128;
    for (int i = tid; i < 8192; i += 256) {
        int c = i >> 7, f = i & 127;
        tile[c][f] = xb[(size_t)c*16384 + f];
    }
    __syncthreads();
    if (tid < 128) {
        float s = 0.f, ss = 0.f;
        #pragma unroll
        for (int c = 0; c < 64; c++) { float v = tile[c][tid]; s += v; ss += v*v; }
        float m = s * 0.015625f;
        msh[tid] = m;
        rsh[tid] = rsqrtf(ss * 0.015625f - m*m + 1e-5f);
    }
    __syncthreads();
    for (int i = tid; i < 8192; i += 256) {
        int f = i >> 6, c = i & 63;
        int row = stage ? ((b << 7) + f)*128 + t : ((b << 7) + t)*128 + f;
        g_u[(size_t)row*64 + c] = (tile[c][f] - msh[f]) * rsh[f] * wsh[c] + bsh[c];
    }
}

// ============================================================
// in_proj GEMM, both directions. M=65536, N=768, K=64.
// ============================================================
#define GKC 16
__global__ __launch_bounds__(256, 2) void gemm_in(const float* __restrict__ Wf,
                                                  const float* __restrict__ Wb)
{
    __shared__ __align__(16) float As2[GKC][264];
    __shared__ __align__(16) float Bs[GKC][132];
    int bx = blockIdx.x;
    int dir = (bx >= 3);
    const float* W = dir ? Wb : Wf;
    int j0 = (bx - dir*3) * 128;
    size_t bm = (size_t)blockIdx.y * 128;
    int tid = threadIdx.x;
    int tr = tid >> 4, tc = tid & 15;
    float2 acc[8][4];
    #pragma unroll
    for (int i = 0; i < 8; i++)
        #pragma unroll
        for (int j = 0; j < 4; j++) acc[i][j] = make_float2(0.f, 0.f);

    for (int k0 = 0; k0 < 64; k0 += GKC) {
        #pragma unroll
        for (int t = 0; t < 2; t++) {
            int i = tid + t*256;
            int m = i >> 2, kg = (i & 3) * 4;
            float4 v = *(const float4*)&g_u[(bm + m)*64 + k0 + kg];
            *(float2*)&As2[kg+0][2*m] = make_float2(v.x, v.x);
            *(float2*)&As2[kg+1][2*m] = make_float2(v.y, v.y);
            *(float2*)&As2[kg+2][2*m] = make_float2(v.z, v.z);
            *(float2*)&As2[kg+3][2*m] = make_float2(v.w, v.w);
        }
        #pragma unroll
        for (int t = 0; t < 2; t++) {
            int i = tid + t*256;
            int n = i >> 2, kg = (i & 3) * 4;
            float4 v = *(const float4*)&W[(size_t)(j0 + n)*64 + k0 + kg];
            Bs[kg+0][n] = v.x; Bs[kg+1][n] = v.y; Bs[kg+2][n] = v.z; Bs[kg+3][n] = v.w;
        }
        __syncthreads();
        #pragma unroll
        for (int k = 0; k < GKC; k++) {
            float4 a01 = *(const float4*)&As2[k][tr*16];
            float4 a23 = *(const float4*)&As2[k][tr*16 + 4];
            float4 a45 = *(const float4*)&As2[k][tr*16 + 8];
            float4 a67 = *(const float4*)&As2[k][tr*16 + 12];
            float4 b03 = *(const float4*)&Bs[k][tc*8];
            float4 b47 = *(const float4*)&Bs[k][tc*8 + 4];
            float2 a2[8] = { {a01.x,a01.y},{a01.z,a01.w},{a23.x,a23.y},{a23.z,a23.w},
                             {a45.x,a45.y},{a45.z,a45.w},{a67.x,a67.y},{a67.z,a67.w} };
            float2 b2[4] = { {b03.x,b03.y},{b03.z,b03.w},{b47.x,b47.y},{b47.z,b47.w} };
            #pragma unroll
            for (int ii = 0; ii < 8; ii++)
                #pragma unroll
                for (int jj = 0; jj < 4; jj++)
                    acc[ii][jj] = ffma2(a2[ii], b2[jj], acc[ii][jj]);
        }
        __syncthreads();
    }
    float* Cout = g_zx[dir];
    #pragma unroll
    for (int ii = 0; ii < 8; ii++) {
        size_t m = bm + tr*8 + ii;
        float4 o0 = make_float4(acc[ii][0].x, acc[ii][0].y, acc[ii][1].x, acc[ii][1].y);
        float4 o1 = make_float4(acc[ii][2].x, acc[ii][2].y, acc[ii][3].x, acc[ii][3].y);
        *(float4*)&Cout[m*384 + j0 + tc*8]     = o0;
        *(float4*)&Cout[m*384 + j0 + tc*8 + 4] = o1;
    }
}

// ============================================================
// dt precompute: g_dt[dir][r] = {dt0, dt1, ldA0, ldA1}, ldA = -exp(Alog)*dt
// ============================================================
__global__ __launch_bounds__(256) void dt_kernel(const float* __restrict__ inW,
        const float* __restrict__ dtb, const float* __restrict__ Alog, int pf, int pb)
{
    __shared__ float usm[128][65];
    __shared__ float wsm[2][2][64];
    __shared__ float par[2][2][2];
    int tid = threadIdx.x;
    int r0 = blockIdx.x * 128;
    for (int i = tid; i < 8192; i += 256) {
        int m = i >> 6, k = i & 63;
        usm[m][k] = g_u[(size_t)(r0 + m)*64 + k];
    }
    {
        int d = tid >> 7, rest = tid & 127, h = rest >> 6, k = rest & 63;
        int pidx = d ? pb : pf;
        wsm[d][h][k] = inW[(size_t)pidx*386*64 + (384 + h)*64 + k];
    }
    if (tid < 4) {
        int d = tid >> 1, h = tid & 1;
        int pidx = d ? pb : pf;
        par[d][h][0] = dtb[pidx*2 + h];
        par[d][h][1] = -expf(Alog[pidx*2 + h]);
    }
    __syncthreads();
    int rl = tid & 127, d = tid >> 7;
    float out[4];
    #pragma unroll
    for (int h = 0; h < 2; h++) {
        float acc = 0.f;
        #pragma unroll
        for (int k = 0; k < 64; k++) acc = fmaf(usm[rl][k], wsm[d][h][k], acc);
        float xr = acc + par[d][h][0];
        float dt = (xr > 20.f) ? xr : log1pf(expf(xr));
        out[h] = dt;
        out[2 + h] = par[d][h][1] * dt;   // log dA
    }
    float* o = &g_dt[d][(size_t)(r0 + rl)*4];
    o[0] = out[0]; o[1] = out[1]; o[2] = out[2]; o[3] = out[3];
}

// ============================================================
// Fused SSD with folded (balanced) t-mapping.
// 512 threads, one block per (seq, dir).
// smem (floats):
//   X  @ 0     : [128 l][132]        conv'd x
//   BT @ 16896 : [64 n][132 s]       conv'd B^T
//   CT @ 25344 : [64 n][132 t]       conv'd C^T
//   G2 @ 33792 : [64 tl][130 s][2 h] decayed scores (per t-panel)
//   LL @ 50432 : [2][128] ; DT @ 50688 : [2][128]
// ============================================================
#define SMX 0
#define SMBT 16896
#define SMCT 25344
#define SMG 33792
#define SMLL 50432
#define SMDT 50688
#define SSD_SMEM_FLOATS 50944
#define SSD_SMEM_BYTES (SSD_SMEM_FLOATS*4)

// P row: pacc[j] = (P[t][s0+2j], P[t][s0+2j+1])
__device__ __forceinline__ void gemm1_row(const float* __restrict__ sm,
                                          int t, int s0, float2 pacc[4])
{
    pacc[0] = pacc[1] = pacc[2] = pacc[3] = make_float2(0.f, 0.f);
    #pragma unroll 4
    for (int n = 0; n < 64; n++) {
        float2 c = dup2(sm[SMCT + n*132 + t]);
        float4 b0 = *(const float4*)&sm[SMBT + n*132 + s0];
        float4 b1 = *(const float4*)&sm[SMBT + n*132 + s0 + 4];
        pacc[0] = ffma2(c, make_float2(b0.x, b0.y), pacc[0]);
        pacc[1] = ffma2(c, make_float2(b0.z, b0.w), pacc[1]);
        pacc[2] = ffma2(c, make_float2(b1.x, b1.y), pacc[2]);
        pacc[3] = ffma2(c, make_float2(b1.z, b1.w), pacc[3]);
    }
}

// G2[tl][s] = {P*dt0_s*exp(ll0_t-ll0_s), P*dt1_s*exp(ll1_t-ll1_s)}, masked s<=t
__device__ __forceinline__ void decay_store(float* __restrict__ sm,
                                            int t, int base, int s0,
                                            const float2 pacc[4])
{
    int tl = t - base;
    float llt0 = sm[SMLL + t];
    float llt1 = sm[SMLL + 128 + t];
    float* gbase = sm + SMG + (tl*130 + s0)*2;
    #pragma unroll
    for (int j2 = 0; j2 < 4; j2++) {
        float pv0 = pacc[j2].x, pv1 = pacc[j2].y;
        int sg0 = s0 + 2*j2, sg1 = sg0 + 1;
        float4 out;
        float d00 = sm[SMDT + sg0],       l00 = sm[SMLL + sg0];
        float d10 = sm[SMDT + 128 + sg0], l10 = sm[SMLL + 128 + sg0];
        out.x = (sg0 <= t) ? pv0 * d00 * __expf(llt0 - l00) : 0.f;
        out.y = (sg0 <= t) ? pv0 * d10 * __expf(llt1 - l10) : 0.f;
        float d01 = sm[SMDT + sg1],       l01 = sm[SMLL + sg1];
        float d11 = sm[SMDT + 128 + sg1], l11 = sm[SMLL + 128 + sg1];
        out.z = (sg1 <= t) ? pv1 * d01 * __expf(llt0 - l01) : 0.f;
        out.w = (sg1 <= t) ? pv1 * d11 * __expf(llt1 - l11) : 0.f;
        *(float4*)&gbase[4*j2] = out;
    }
}

__global__ __launch_bounds__(512, 1) void ssd_kernel(
    const float* __restrict__ convW, const float* __restrict__ convB,
    const float* __restrict__ Dp, const float* __restrict__ normw, int pf, int pb)
{
    extern __shared__ float sm[];
    int blk = blockIdx.x, dir = blk >> 9, s = blk & 511;
    int pidx = dir ? pb : pf;
    int tid = threadIdx.x;
    const float* zxa = g_zx[dir] + (size_t)s * L_ * 384;

    // ---- phase 0: depthwise conv(k=4, causal) + silu into smem (transposed
    //      for B/C). 512 thr = 256 ch x 2 l-halves.
    {
        int ch = tid & 255, hf = tid >> 8;
        float cw0 = convW[pidx*1024 + ch*4 + 0];
        float cw1 = convW[pidx*1024 + ch*4 + 1];
        float cw2 = convW[pidx*1024 + ch*4 + 2];
        float cw3 = convW[pidx*1024 + ch*4 + 3];
        float cb  = convB[pidx*256 + ch];
        const float* src = zxa + 128 + ch;
        float* obase;
        int ostep;
        if (ch < 128)      { obase = sm + SMX + ch;              ostep = 132; }
        else if (ch < 192) { obase = sm + SMBT + (ch-128)*132;   ostep = 1;   }
        else               { obase = sm + SMCT + (ch-192)*132;   ostep = 1;   }
        int ls = hf * 64;
        float xm3 = 0.f, xm2 = 0.f, xm1 = 0.f;
        #pragma unroll
        for (int j = 0; j < 3; j++) {
            int l = ls - 3 + j;
            float v = 0.f;
            if (l >= 0) v = src[(size_t)(dir ? 127-l : l)*384];
            xm3 = xm2; xm2 = xm1; xm1 = v;
        }
        float nxt[4];
        #pragma unroll
        for (int j = 0; j < 4; j++)
            nxt[j] = src[(size_t)(dir ? 127-(ls+j) : (ls+j))*384];
        for (int lb = 0; lb < 64; lb += 4) {
            float cur[4];
            #pragma unroll
            for (int j = 0; j < 4; j++) cur[j] = nxt[j];
            if (lb + 4 < 64) {
                #pragma unroll
                for (int j = 0; j < 4; j++) {
                    int l = ls + lb + 4 + j;
                    nxt[j] = src[(size_t)(dir ? 127-l : l)*384];
                }
            }
            #pragma unroll
            for (int j = 0; j < 4; j++) {
                float v = cur[j];
                float acc = cb;
                acc = fmaf(cw0, xm3, acc);
                acc = fmaf(cw1, xm2, acc);
                acc = fmaf(cw2, xm1, acc);
                acc = fmaf(cw3, v,   acc);
                xm3 = xm2; xm2 = xm1; xm1 = v;
                float y = acc / (1.f + expf(-acc));
                obase[(ls + lb + j) * ostep] = y;
            }
        }
    }
    // ---- LL prefix scan + dt (warps 0,1) ----
    if (tid < 64) {
        int h = tid >> 5, lane = tid & 31;
        float carry = 0.f;
        for (int c = 0; c < 4; c++) {
            int l = c*32 + lane;
            int lp = dir ? 127 - l : l;
            const float* dr = g_dt[dir] + ((size_t)s*128 + lp)*4;
            sm[SMDT + h*128 + l] = dr[h];
            float v = dr[2 + h];
            #pragma unroll
            for (int o = 1; o < 32; o <<= 1) {
                float t = __shfl_up_sync(0xffffffffu, v, o);
                if (lane >= o) v += t;
            }
            sm[SMLL + h*128 + l] = v + carry;
            carry += __shfl_sync(0xffffffffu, v, 31);
        }
    }
    __syncthreads();

    int ti = tid >> 4, pi = tid & 15;
    int s0 = pi * 8;
    float2 acc[4][2][2];   // [row: p0lo,p0hi,p1lo,p1hi][head][f2]
    #pragma unroll
    for (int r = 0; r < 4; r++)
        #pragma unroll
        for (int h = 0; h < 2; h++) {
            acc[r][h][0] = make_float2(0.f, 0.f);
            acc[r][h][1] = make_float2(0.f, 0.f);
        }

    #pragma unroll
    for (int p = 0; p < 2; p++) {
        int base = 64 * p;
        int tlo = base + ti, thi = base + 63 - ti;
        // ---- GEMM1 + fused decay (folded rows; ~balanced) ----
        {
            float2 pacc[4];
            if (s0 <= tlo + 1) {
                gemm1_row(sm, tlo, s0, pacc);
                decay_store(sm, tlo, base, s0, pacc);
            }
            if (s0 <= thi + 1) {
                gemm1_row(sm, thi, s0, pacc);
                decay_store(sm, thi, base, s0, pacc);
            }
        }
        __syncthreads();
        // ---- GEMM2 (constant work per thread: klo+khi = 2*base+67) ----
        int tl_lo = ti, tl_hi = 63 - ti;
        int klo = tlo + 2; if (klo > 128) klo = 128;
        int khi = thi + 2; if (khi > 128) khi = 128;
        int rlo = 2*p, rhi = 2*p + 1;
        for (int sg = 0; sg < khi; sg++) {
            float4 x0 = *(const float4*)&sm[SMX + sg*132 + pi*4];
            float4 x1 = *(const float4*)&sm[SMX + sg*132 + 64 + pi*4];
            float2 xb00 = make_float2(x0.x, x0.y), xb01 = make_float2(x0.z, x0.w);
            float2 xb10 = make_float2(x1.x, x1.y), xb11 = make_float2(x1.z, x1.w);
            float2 gh = *(const float2*)&sm[SMG + (tl_hi*130 + sg)*2];
            acc[rhi][0][0] = ffma2(dup2(gh.x), xb00, acc[rhi][0][0]);
            acc[rhi][0][1] = ffma2(dup2(gh.x), xb01, acc[rhi][0][1]);
            acc[rhi][1][0] = ffma2(dup2(gh.y), xb10, acc[rhi][1][0]);
            acc[rhi][1][1] = ffma2(dup2(gh.y), xb11, acc[rhi][1][1]);
            if (sg < klo) {
                float2 gl = *(const float2*)&sm[SMG + (tl_lo*130 + sg)*2];
                acc[rlo][0][0] = ffma2(dup2(gl.x), xb00, acc[rlo][0][0]);
                acc[rlo][0][1] = ffma2(dup2(gl.x), xb01, acc[rlo][0][1]);
                acc[rlo][1][0] = ffma2(dup2(gl.y), xb10, acc[rlo][1][0]);
                acc[rlo][1][1] = ffma2(dup2(gl.y), xb11, acc[rlo][1][1]);
            }
        }
        __syncthreads();
    }

    // ---- epilogue: +D*x, gate silu(z), rmsnorm(128), *norm_w -> g_gbuf ----
    {
        float Dv0 = Dp[pidx*2], Dv1 = Dp[pidx*2 + 1];
        float4 nw0 = *(const float4*)&normw[pidx*128 + pi*4];
        float4 nw1 = *(const float4*)&normw[pidx*128 + 64 + pi*4];
        int tv[4] = {ti, 63 - ti, 64 + ti, 127 - ti};
        #pragma unroll
        for (int r = 0; r < 4; r++) {
            int t = tv[r];
            int lp = dir ? 127 - t : t;
            float4 x0 = *(const float4*)&sm[SMX + t*132 + pi*4];
            float4 x1 = *(const float4*)&sm[SMX + t*132 + 64 + pi*4];
            const float* zr = zxa + (size_t)lp*384;
            float4 z0 = *(const float4*)&zr[pi*4];
            float4 z1 = *(const float4*)&zr[64 + pi*4];
            float g[8];
            g[0] = fmaf(Dv0, x0.x, acc[r][0][0].x);
            g[1] = fmaf(Dv0, x0.y, acc[r][0][0].y);
            g[2] = fmaf(Dv0, x0.z, acc[r][0][1].x);
            g[3] = fmaf(Dv0, x0.w, acc[r][0][1].y);
            g[4] = fmaf(Dv1, x1.x, acc[r][1][0].x);
            g[5] = fmaf(Dv1, x1.y, acc[r][1][0].y);
            g[6] = fmaf(Dv1, x1.z, acc[r][1][1].x);
            g[7] = fmaf(Dv1, x1.w, acc[r][1][1].y);
            float z[8] = {z0.x, z0.y, z0.z, z0.w, z1.x, z1.y, z1.z, z1.w};
            float ss = 0.f;
            #pragma unroll
            for (int j = 0; j < 8; j++) {
                g[j] = g[j] * (z[j] / (1.f + expf(-z[j])));
                ss = fmaf(g[j], g[j], ss);
            }
            ss += __shfl_xor_sync(0xffffffffu, ss, 1);
            ss += __shfl_xor_sync(0xffffffffu, ss, 2);
            ss += __shfl_xor_sync(0xffffffffu, ss, 4);
            ss += __shfl_xor_sync(0xffffffffu, ss, 8);
            float rs = rsqrtf(ss * 0.0078125f + 1e-5f);
            float* go = g_gbuf + ((size_t)s*128 + lp)*256 + (dir << 7);
            *(float4*)&go[pi*4]      = make_float4(g[0]*rs*nw0.x, g[1]*rs*nw0.y,
                                                   g[2]*rs*nw0.z, g[3]*rs*nw0.w);
            *(float4*)&go[64 + pi*4] = make_float4(g[4]*rs*nw1.x, g[5]*rs*nw1.y,
                                                   g[6]*rs*nw1.z, g[7]*rs*nw1.w);
        }
    }
}

// ============================================================
// Fold out_proj x fusion
// ============================================================
__global__ void wc_kernel(const float* __restrict__ fW, const float* __restrict__ oW,
                          int pf, int pb)
{
    int idx = blockIdx.x*256 + threadIdx.x;
    int m = idx >> 8, r = idx & 255, dir = r >> 7, j = r & 127;
    int pidx = dir ? pb : pf;
    const float* wo = oW + (size_t)pidx*64*128;
    const float* wf = fW + m*128 + (dir << 6);
    float acc = 0.f;
    #pragma unroll
    for (int i = 0; i < 64; i++) acc = fmaf(wf[i], wo[i*128 + j], acc);
    g_wc[idx] = acc;
}

// ============================================================
// final GEMM + residual + scatter. M=65536, N=64, K=256.
// ============================================================
__global__ __launch_bounds__(256) void gemm_out(const float* __restrict__ fb,
        const float* __restrict__ x_ext, float* __restrict__ out_ext, int stage)
{
    __shared__ __align__(16) float As[16][68];
    __shared__ __align__(16) float Ws[16][68];
    const float* xin = stage ? g_xwork : x_ext;
    float* xout = stage ? out_ext : g_xwork;
    size_t bm = (size_t)blockIdx.x * 64;
    int tid = threadIdx.x, tr = tid >> 4, tc = tid & 15;
    float acc[4][4] = {};
    for (int k0 = 0; k0 < 256; k0 += 16) {
        #pragma unroll
        for (int i = tid; i < 1024; i += 256) {
            int m = i >> 4, k = i & 15;
            As[k][m] = g_gbuf[(bm + m)*256 + k0 + k];
        }
        #pragma unroll
        for (int i = tid; i < 1024; i += 256) {
            int n = i >> 4, k = i & 15;
            Ws[k][n] = g_wc[n*256 + k0 + k];
        }
        __syncthreads();
        #pragma unroll
        for (int k = 0; k < 16; k++) {
            float a[4], b4[4];
            *(float4*)a  = *(const float4*)&As[k][tr*4];
            *(float4*)b4 = *(const float4*)&Ws[k][tc*4];
            #pragma unroll
            for (int ii = 0; ii < 4; ii++)
                #pragma unroll
                for (int jj = 0; jj < 4; jj++)
                    acc[ii][jj] = fmaf(a[ii], b4[jj], acc[ii][jj]);
        }
        __syncthreads();
    }
    #pragma unroll
    for (int ii = 0; ii < 4; ii++) {
        size_t r = bm + tr*4 + ii;
        int b = (int)(r >> 14), low = (int)(r & 16383);
        int t_, f_;
        if (stage == 0) { t_ = low >> 7; f_ = low & 127; }
        else            { f_ = low >> 7; t_ = low & 127; }
        #pragma unroll
        for (int jj = 0; jj < 4; jj++) {
            int n = tc*4 + jj;
            size_t idx = (((size_t)(b*64 + n)*128) + t_)*128 + f_;
            xout[idx] = xin[idx] + acc[ii][jj] + fb[n];
        }
    }
}

// ============================================================
extern "C" void kernel_launch(void* const* d_in, const int* in_sizes, int n_in,
                              void* d_out, int out_size)
{
    const float* x     = (const float*)d_in[0];
    const float* inW   = (const float*)d_in[1];
    const float* convW = (const float*)d_in[2];
    const float* convB = (const float*)d_in[3];
    const float* dtb   = (const float*)d_in[4];
    const float* Alog  = (const float*)d_in[5];
    const float* Dp    = (const float*)d_in[6];
    const float* nw    = (const float*)d_in[7];
    const float* outW  = (const float*)d_in[8];
    const float* fW    = (const float*)d_in[9];
    const float* fb    = (const float*)d_in[10];
    const float* lnw   = (const float*)d_in[11];
    const float* lnb   = (const float*)d_in[12];
    float* out = (float*)d_out;

    cudaFuncSetAttribute(ssd_kernel, cudaFuncAttributeMaxDynamicSharedMemorySize,
                         SSD_SMEM_BYTES);

    for (int st = 0; st < 2; st++) {
        int pf = 2*st, pb = 2*st + 1;
        ln_kernel<<<512, 256>>>(x, lnw + st*64, lnb + st*64, st);
        gemm_in<<<dim3(6, 512), 256>>>(inW + (size_t)pf*386*64, inW + (size_t)pb*386*64);
        dt_kernel<<<512, 256>>>(inW, dtb, Alog, pf, pb);
        ssd_kernel<<<1024, 512, SSD_SMEM_BYTES>>>(convW, convB, Dp, nw, pf, pb);
        wc_kernel<<<64, 256>>>(fW + st*64*128, outW, pf, pb);
        gemm_out<<<1024, 256>>>(fb + st*64, x, out, st);
    }
}

// round 7
// speedup vs baseline: 1.1701x; 1.1701x over previous
#include <cuda_runtime.h>
#include <math.h>

#define S_ 512
#define L_ 128

// ---- packed f32x2 helpers ----
__device__ __forceinline__ float2 ffma2(float2 a, float2 b, float2 c) {
    unsigned long long ua = *reinterpret_cast<unsigned long long*>(&a);
    unsigned long long ub = *reinterpret_cast<unsigned long long*>(&b);
    unsigned long long uc = *reinterpret_cast<unsigned long long*>(&c);
    unsigned long long ud;
    asm("fma.rn.f32x2 %0, %1, %2, %3;" : "=l"(ud) : "l"(ua), "l"(ub), "l"(uc));
    return *reinterpret_cast<float2*>(&ud);
}
__device__ __forceinline__ float2 dup2(float a) {
    unsigned long long u;
    asm("mov.b64 %0, {%1, %1};" : "=l"(u) : "f"(a));
    return *reinterpret_cast<float2*>(&u);
}

// ---- scratch ----
__device__ __align__(16) float g_xwork[(size_t)4*64*128*128];
__device__ __align__(16) float g_u[(size_t)S_*L_*64];
__device__ __align__(16) float g_zx[2][(size_t)S_*L_*384];   // z | raw xBC
__device__ __align__(16) float g_dt[2][(size_t)S_*L_*4];     // {dt0,dt1,ldA0,ldA1}
__device__ __align__(16) float g_gbuf[(size_t)S_*L_*256];
__device__ __align__(16) float g_wc[64*256];

// ============================================================
// LayerNorm over channels + layout to (seq, pos, ch)
// ============================================================
__global__ void ln_kernel(const float* __restrict__ x_ext,
                          const float* __restrict__ lnw, const float* __restrict__ lnb,
                          int stage)
{
    __shared__ float tile[64][133];
    __shared__ float msh[128], rsh[128], wsh[64], bsh[64];
    const float* xin = stage ? g_xwork : x_ext;
    int bt = blockIdx.x, b = bt >> 7, t = bt & 127;
    int tid = threadIdx.x;
    if (tid < 64) { wsh[tid] = lnw[tid]; bsh[tid] = lnb[tid]; }
    const float* xb = xin + ((size_t)b*64*128 + t)*128;
    for (int i = tid; i < 8192; i += 256) {
        int c = i >> 7, f = i & 127;
        tile[c][f] = xb[(size_t)c*16384 + f];
    }
    __syncthreads();
    if (tid < 128) {
        float s = 0.f, ss = 0.f;
        #pragma unroll
        for (int c = 0; c < 64; c++) { float v = tile[c][tid]; s += v; ss += v*v; }
        float m = s * 0.015625f;
        msh[tid] = m;
        rsh[tid] = rsqrtf(ss * 0.015625f - m*m + 1e-5f);
    }
    __syncthreads();
    for (int i = tid; i < 8192; i += 256) {
        int f = i >> 6, c = i & 63;
        int row = stage ? ((b << 7) + f)*128 + t : ((b << 7) + t)*128 + f;
        g_u[(size_t)row*64 + c] = (tile[c][f] - msh[f]) * rsh[f] * wsh[c] + bsh[c];
    }
}

// ============================================================
// in_proj GEMM, both directions. M=65536, N=768, K=64.
// ============================================================
#define GKC 16
__global__ __launch_bounds__(256, 2) void gemm_in(const float* __restrict__ Wf,
                                                  const float* __restrict__ Wb)
{
    __shared__ __align__(16) float As2[GKC][264];
    __shared__ __align__(16) float Bs[GKC][132];
    int bx = blockIdx.x;
    int dir = (bx >= 3);
    const float* W = dir ? Wb : Wf;
    int j0 = (bx - dir*3) * 128;
    size_t bm = (size_t)blockIdx.y * 128;
    int tid = threadIdx.x;
    int tr = tid >> 4, tc = tid & 15;
    float2 acc[8][4];
    #pragma unroll
    for (int i = 0; i < 8; i++)
        #pragma unroll
        for (int j = 0; j < 4; j++) acc[i][j] = make_float2(0.f, 0.f);

    for (int k0 = 0; k0 < 64; k0 += GKC) {
        #pragma unroll
        for (int t = 0; t < 2; t++) {
            int i = tid + t*256;
            int m = i >> 2, kg = (i & 3) * 4;
            float4 v = *(const float4*)&g_u[(bm + m)*64 + k0 + kg];
            *(float2*)&As2[kg+0][2*m] = make_float2(v.x, v.x);
            *(float2*)&As2[kg+1][2*m] = make_float2(v.y, v.y);
            *(float2*)&As2[kg+2][2*m] = make_float2(v.z, v.z);
            *(float2*)&As2[kg+3][2*m] = make_float2(v.w, v.w);
        }
        #pragma unroll
        for (int t = 0; t < 2; t++) {
            int i = tid + t*256;
            int n = i >> 2, kg = (i & 3) * 4;
            float4 v = *(const float4*)&W[(size_t)(j0 + n)*64 + k0 + kg];
            Bs[kg+0][n] = v.x; Bs[kg+1][n] = v.y; Bs[kg+2][n] = v.z; Bs[kg+3][n] = v.w;
        }
        __syncthreads();
        #pragma unroll
        for (int k = 0; k < GKC; k++) {
            float4 a01 = *(const float4*)&As2[k][tr*16];
            float4 a23 = *(const float4*)&As2[k][tr*16 + 4];
            float4 a45 = *(const float4*)&As2[k][tr*16 + 8];
            float4 a67 = *(const float4*)&As2[k][tr*16 + 12];
            float4 b03 = *(const float4*)&Bs[k][tc*8];
            float4 b47 = *(const float4*)&Bs[k][tc*8 + 4];
            float2 a2[8] = { {a01.x,a01.y},{a01.z,a01.w},{a23.x,a23.y},{a23.z,a23.w},
                             {a45.x,a45.y},{a45.z,a45.w},{a67.x,a67.y},{a67.z,a67.w} };
            float2 b2[4] = { {b03.x,b03.y},{b03.z,b03.w},{b47.x,b47.y},{b47.z,b47.w} };
            #pragma unroll
            for (int ii = 0; ii < 8; ii++)
                #pragma unroll
                for (int jj = 0; jj < 4; jj++)
                    acc[ii][jj] = ffma2(a2[ii], b2[jj], acc[ii][jj]);
        }
        __syncthreads();
    }
    float* Cout = g_zx[dir];
    #pragma unroll
    for (int ii = 0; ii < 8; ii++) {
        size_t m = bm + tr*8 + ii;
        float4 o0 = make_float4(acc[ii][0].x, acc[ii][0].y, acc[ii][1].x, acc[ii][1].y);
        float4 o1 = make_float4(acc[ii][2].x, acc[ii][2].y, acc[ii][3].x, acc[ii][3].y);
        *(float4*)&Cout[m*384 + j0 + tc*8]     = o0;
        *(float4*)&Cout[m*384 + j0 + tc*8 + 4] = o1;
    }
}

// ============================================================
// dt precompute: g_dt[dir][r] = {dt0, dt1, ldA0, ldA1}, ldA = -exp(Alog)*dt
// ============================================================
__global__ __launch_bounds__(256) void dt_kernel(const float* __restrict__ inW,
        const float* __restrict__ dtb, const float* __restrict__ Alog, int pf, int pb)
{
    __shared__ float usm[128][65];
    __shared__ float wsm[2][2][64];
    __shared__ float par[2][2][2];
    int tid = threadIdx.x;
    int r0 = blockIdx.x * 128;
    for (int i = tid; i < 8192; i += 256) {
        int m = i >> 6, k = i & 63;
        usm[m][k] = g_u[(size_t)(r0 + m)*64 + k];
    }
    {
        int d = tid >> 7, rest = tid & 127, h = rest >> 6, k = rest & 63;
        int pidx = d ? pb : pf;
        wsm[d][h][k] = inW[(size_t)pidx*386*64 + (384 + h)*64 + k];
    }
    if (tid < 4) {
        int d = tid >> 1, h = tid & 1;
        int pidx = d ? pb : pf;
        par[d][h][0] = dtb[pidx*2 + h];
        par[d][h][1] = -expf(Alog[pidx*2 + h]);
    }
    __syncthreads();
    int rl = tid & 127, d = tid >> 7;
    float out[4];
    #pragma unroll
    for (int h = 0; h < 2; h++) {
        float acc = 0.f;
        #pragma unroll
        for (int k = 0; k < 64; k++) acc = fmaf(usm[rl][k], wsm[d][h][k], acc);
        float xr = acc + par[d][h][0];
        float dt = (xr > 20.f) ? xr : log1pf(expf(xr));
        out[h] = dt;
        out[2 + h] = par[d][h][1] * dt;   // log dA
    }
    float* o = &g_dt[d][(size_t)(r0 + rl)*4];
    o[0] = out[0]; o[1] = out[1]; o[2] = out[2]; o[3] = out[3];
}

// ============================================================
// Fused SSD (R5 layout — best measured): conv+silu -> GEMM1+decay
// (s-panels) -> GEMM2 (triangular) -> epilogue. 512 threads.
// smem (floats):
//   X  @ 0     : [128 l][132]  conv'd x
//   BT @ 16896 : [64 n][132]   conv'd B^T
//   CT @ 25344 : [64 n][132]   conv'd C^T
//   G  @ 33792 : [2 h][64 s][132]  per-panel decayed scores
//   LL @ 50688 : [2][128] ; DT @ 50944 : [2][128]
// ============================================================
#define SMX 0
#define SMBT 16896
#define SMCT 25344
#define SMG 33792
#define SMLL 50688
#define SMDT 50944
#define SSD_SMEM_FLOATS 51200
#define SSD_SMEM_BYTES (SSD_SMEM_FLOATS*4)

__global__ __launch_bounds__(512, 1) void ssd_kernel(
    const float* __restrict__ convW, const float* __restrict__ convB,
    const float* __restrict__ Dp, const float* __restrict__ normw, int pf, int pb)
{
    extern __shared__ float sm[];
    int blk = blockIdx.x, dir = blk >> 9, s = blk & 511;
    int pidx = dir ? pb : pf;
    int tid = threadIdx.x;
    const float* zxa = g_zx[dir] + (size_t)s * L_ * 384;

    // ---- phase 0: depthwise conv(k=4, causal) + silu into smem ----
    {
        int ch = tid & 255, hf = tid >> 8;
        float cw0 = convW[pidx*1024 + ch*4 + 0];
        float cw1 = convW[pidx*1024 + ch*4 + 1];
        float cw2 = convW[pidx*1024 + ch*4 + 2];
        float cw3 = convW[pidx*1024 + ch*4 + 3];
        float cb  = convB[pidx*256 + ch];
        const float* src = zxa + 128 + ch;
        float* obase;
        int ostep;
        if (ch < 128)      { obase = sm + SMX + ch;              ostep = 132; }
        else if (ch < 192) { obase = sm + SMBT + (ch-128)*132;   ostep = 1;   }
        else               { obase = sm + SMCT + (ch-192)*132;   ostep = 1;   }
        int ls = hf * 64;
        float xm3 = 0.f, xm2 = 0.f, xm1 = 0.f;
        #pragma unroll
        for (int j = 0; j < 3; j++) {
            int l = ls - 3 + j;
            float v = 0.f;
            if (l >= 0) v = src[(size_t)(dir ? 127-l : l)*384];
            xm3 = xm2; xm2 = xm1; xm1 = v;
        }
        float nxt[4];
        #pragma unroll
        for (int j = 0; j < 4; j++)
            nxt[j] = src[(size_t)(dir ? 127-(ls+j) : (ls+j))*384];
        for (int lb = 0; lb < 64; lb += 4) {
            float cur[4];
            #pragma unroll
            for (int j = 0; j < 4; j++) cur[j] = nxt[j];
            if (lb + 4 < 64) {
                #pragma unroll
                for (int j = 0; j < 4; j++) {
                    int l = ls + lb + 4 + j;
                    nxt[j] = src[(size_t)(dir ? 127-l : l)*384];
                }
            }
            #pragma unroll
            for (int j = 0; j < 4; j++) {
                float v = cur[j];
                float acc = cb;
                acc = fmaf(cw0, xm3, acc);
                acc = fmaf(cw1, xm2, acc);
                acc = fmaf(cw2, xm1, acc);
                acc = fmaf(cw3, v,   acc);
                xm3 = xm2; xm2 = xm1; xm1 = v;
                float y = acc / (1.f + expf(-acc));
                obase[(ls + lb + j) * ostep] = y;
            }
        }
    }
    // ---- LL prefix scan + dt (warps 0,1) ----
    if (tid < 64) {
        int h = tid >> 5, lane = tid & 31;
        float carry = 0.f;
        for (int c = 0; c < 4; c++) {
            int l = c*32 + lane;
            int lp = dir ? 127 - l : l;
            const float* dr = g_dt[dir] + ((size_t)s*128 + lp)*4;
            sm[SMDT + h*128 + l] = dr[h];
            float v = dr[2 + h];
            #pragma unroll
            for (int o = 1; o < 32; o <<= 1) {
                float t = __shfl_up_sync(0xffffffffu, v, o);
                if (lane >= o) v += t;
            }
            sm[SMLL + h*128 + l] = v + carry;
            carry += __shfl_sync(0xffffffffu, v, 31);
        }
    }
    __syncthreads();

    int ti = tid >> 4;          // 0..31 (4 t-rows each)
    int pi = tid & 15;
    int t0 = ti * 4;
    float2 accY[2][4][2];
    #pragma unroll
    for (int h = 0; h < 2; h++)
        #pragma unroll
        for (int i = 0; i < 4; i++) {
            accY[h][i][0] = make_float2(0.f, 0.f);
            accY[h][i][1] = make_float2(0.f, 0.f);
        }

    #pragma unroll
    for (int p = 0; p < 2; p++) {
        int s_base = p * 64;
        int s0 = s_base + pi * 4;
        // ---- GEMM1: pacc[t 4][s 4] = sum_n C[t][n]*B[s][n] ----
        float2 pacc[4][2];
        #pragma unroll
        for (int i = 0; i < 4; i++) {
            pacc[i][0] = make_float2(0.f, 0.f);
            pacc[i][1] = make_float2(0.f, 0.f);
        }
        if (s0 <= t0 + 3) {
            #pragma unroll 4
            for (int n = 0; n < 64; n++) {
                float4 c4 = *(const float4*)&sm[SMCT + n*132 + t0];
                float4 b4 = *(const float4*)&sm[SMBT + n*132 + s0];
                float a[4] = {c4.x, c4.y, c4.z, c4.w};
                float2 bb[2] = {{b4.x, b4.y}, {b4.z, b4.w}};
                #pragma unroll
                for (int i = 0; i < 4; i++) {
                    float2 aa = dup2(a[i]);
                    pacc[i][0] = ffma2(aa, bb[0], pacc[i][0]);
                    pacc[i][1] = ffma2(aa, bb[1], pacc[i][1]);
                }
            }
        }
        // ---- fused decay: G[h][s-s_base][t] = pacc*dt_s*exp(ll_t-ll_s), s<=t ----
        #pragma unroll
        for (int h = 0; h < 2; h++) {
            float llt[4];
            #pragma unroll
            for (int i = 0; i < 4; i++) llt[i] = sm[SMLL + h*128 + t0 + i];
            #pragma unroll
            for (int j = 0; j < 4; j++) {
                int sg = s0 + j;
                float dts = sm[SMDT + h*128 + sg];
                float lls = sm[SMLL + h*128 + sg];
                float pv[4];
                #pragma unroll
                for (int i = 0; i < 4; i++)
                    pv[i] = (j & 1) ? pacc[i][j>>1].y : pacc[i][j>>1].x;
                float4 g4;
                g4.x = (sg <= t0+0) ? pv[0]*dts*__expf(llt[0]-lls) : 0.f;
                g4.y = (sg <= t0+1) ? pv[1]*dts*__expf(llt[1]-lls) : 0.f;
                g4.z = (sg <= t0+2) ? pv[2]*dts*__expf(llt[2]-lls) : 0.f;
                g4.w = (sg <= t0+3) ? pv[3]*dts*__expf(llt[3]-lls) : 0.f;
                *(float4*)&sm[SMG + (h*64 + sg - s_base)*132 + t0] = g4;
            }
        }
        __syncthreads();
        // ---- GEMM2 partial: Y[t][p] += sum_{s in panel} G[s][t]*X[s][p] ----
        int klim = t0 + 4 - s_base;
        if (klim > 64) klim = 64;
        for (int sl = 0; sl < klim; sl++) {
            int sg = s_base + sl;
            float4 g0 = *(const float4*)&sm[SMG + sl*132 + t0];
            float4 g1 = *(const float4*)&sm[SMG + (64 + sl)*132 + t0];
            float4 x0 = *(const float4*)&sm[SMX + sg*132 + pi*4];
            float4 x1 = *(const float4*)&sm[SMX + sg*132 + 64 + pi*4];
            float2 b00 = {x0.x, x0.y}, b01 = {x0.z, x0.w};
            float2 b10 = {x1.x, x1.y}, b11 = {x1.z, x1.w};
            float ga0[4] = {g0.x, g0.y, g0.z, g0.w};
            float ga1[4] = {g1.x, g1.y, g1.z, g1.w};
            #pragma unroll
            for (int i = 0; i < 4; i++) {
                float2 a0 = dup2(ga0[i]);
                float2 a1 = dup2(ga1[i]);
                accY[0][i][0] = ffma2(a0, b00, accY[0][i][0]);
                accY[0][i][1] = ffma2(a0, b01, accY[0][i][1]);
                accY[1][i][0] = ffma2(a1, b10, accY[1][i][0]);
                accY[1][i][1] = ffma2(a1, b11, accY[1][i][1]);
            }
        }
        __syncthreads();
    }

    // ---- epilogue: +D*x, gate silu(z), rmsnorm(128), *norm_w -> g_gbuf ----
    {
        float Dv0 = Dp[pidx*2], Dv1 = Dp[pidx*2 + 1];
        float4 nw0 = *(const float4*)&normw[pidx*128 + pi*4];
        float4 nw1 = *(const float4*)&normw[pidx*128 + 64 + pi*4];
        #pragma unroll
        for (int i = 0; i < 4; i++) {
            int l = t0 + i;
            int lp = dir ? 127 - l : l;
            float4 x0 = *(const float4*)&sm[SMX + l*132 + pi*4];
            float4 x1 = *(const float4*)&sm[SMX + l*132 + 64 + pi*4];
            const float* zr = zxa + (size_t)lp*384;
            float4 z0 = *(const float4*)&zr[pi*4];
            float4 z1 = *(const float4*)&zr[64 + pi*4];
            float g[8];
            g[0] = fmaf(Dv0, x0.x, accY[0][i][0].x);
            g[1] = fmaf(Dv0, x0.y, accY[0][i][0].y);
            g[2] = fmaf(Dv0, x0.z, accY[0][i][1].x);
            g[3] = fmaf(Dv0, x0.w, accY[0][i][1].y);
            g[4] = fmaf(Dv1, x1.x, accY[1][i][0].x);
            g[5] = fmaf(Dv1, x1.y, accY[1][i][0].y);
            g[6] = fmaf(Dv1, x1.z, accY[1][i][1].x);
            g[7] = fmaf(Dv1, x1.w, accY[1][i][1].y);
            float z[8] = {z0.x, z0.y, z0.z, z0.w, z1.x, z1.y, z1.z, z1.w};
            float ss = 0.f;
            #pragma unroll
            for (int j = 0; j < 8; j++) {
                g[j] = g[j] * (z[j] / (1.f + expf(-z[j])));
                ss = fmaf(g[j], g[j], ss);
            }
            ss += __shfl_xor_sync(0xffffffffu, ss, 1);
            ss += __shfl_xor_sync(0xffffffffu, ss, 2);
            ss += __shfl_xor_sync(0xffffffffu, ss, 4);
            ss += __shfl_xor_sync(0xffffffffu, ss, 8);
            float rs = rsqrtf(ss * 0.0078125f + 1e-5f);
            float* go = g_gbuf + ((size_t)s*128 + lp)*256 + (dir << 7);
            *(float4*)&go[pi*4]      = make_float4(g[0]*rs*nw0.x, g[1]*rs*nw0.y,
                                                   g[2]*rs*nw0.z, g[3]*rs*nw0.w);
            *(float4*)&go[64 + pi*4] = make_float4(g[4]*rs*nw1.x, g[5]*rs*nw1.y,
                                                   g[6]*rs*nw1.z, g[7]*rs*nw1.w);
        }
    }
}

// ============================================================
// Fold out_proj x fusion
// ============================================================
__global__ void wc_kernel(const float* __restrict__ fW, const float* __restrict__ oW,
                          int pf, int pb)
{
    int idx = blockIdx.x*256 + threadIdx.x;
    int m = idx >> 8, r = idx & 255, dir = r >> 7, j = r & 127;
    int pidx = dir ? pb : pf;
    const float* wo = oW + (size_t)pidx*64*128;
    const float* wf = fW + m*128 + (dir << 6);
    float acc = 0.f;
    #pragma unroll
    for (int i = 0; i < 64; i++) acc = fmaf(wf[i], wo[i*128 + j], acc);
    g_wc[idx] = acc;
}

// ============================================================
// final GEMM + residual + scatter. M=65536, N=64, K=256.
// 128x64 tiles, FFMA2 with duplicated-A smem, 4x8 per thread.
// ============================================================
__global__ __launch_bounds__(256, 2) void gemm_out(const float* __restrict__ fb,
        const float* __restrict__ x_ext, float* __restrict__ out_ext, int stage)
{
    __shared__ __align__(16) float As2[16][264];
    __shared__ __align__(16) float Ws[16][72];
    const float* xin = stage ? g_xwork : x_ext;
    float* xout = stage ? out_ext : g_xwork;
    size_t bm = (size_t)blockIdx.x * 128;
    int tid = threadIdx.x;
    int tr = tid >> 3, tc = tid & 7;    // 32 m-groups x 8 n-groups
    float2 acc[4][4];
    #pragma unroll
    for (int i = 0; i < 4; i++)
        #pragma unroll
        for (int j = 0; j < 4; j++) acc[i][j] = make_float2(0.f, 0.f);

    for (int k0 = 0; k0 < 256; k0 += 16) {
        #pragma unroll
        for (int t = 0; t < 2; t++) {
            int i = tid + t*256;
            int m = i >> 2, kg = (i & 3) * 4;
            float4 v = *(const float4*)&g_gbuf[(bm + m)*256 + k0 + kg];
            *(float2*)&As2[kg+0][2*m] = make_float2(v.x, v.x);
            *(float2*)&As2[kg+1][2*m] = make_float2(v.y, v.y);
            *(float2*)&As2[kg+2][2*m] = make_float2(v.z, v.z);
            *(float2*)&As2[kg+3][2*m] = make_float2(v.w, v.w);
        }
        {
            int n = tid >> 2, kg = (tid & 3) * 4;
            float4 v = *(const float4*)&g_wc[n*256 + k0 + kg];
            Ws[kg+0][n] = v.x; Ws[kg+1][n] = v.y; Ws[kg+2][n] = v.z; Ws[kg+3][n] = v.w;
        }
        __syncthreads();
        #pragma unroll
        for (int k = 0; k < 16; k++) {
            float4 a01 = *(const float4*)&As2[k][tr*8];
            float4 a23 = *(const float4*)&As2[k][tr*8 + 4];
            float4 b03 = *(const float4*)&Ws[k][tc*8];
            float4 b47 = *(const float4*)&Ws[k][tc*8 + 4];
            float2 a2[4] = { {a01.x,a01.y},{a01.z,a01.w},{a23.x,a23.y},{a23.z,a23.w} };
            float2 b2[4] = { {b03.x,b03.y},{b03.z,b03.w},{b47.x,b47.y},{b47.z,b47.w} };
            #pragma unroll
            for (int ii = 0; ii < 4; ii++)
                #pragma unroll
                for (int jj = 0; jj < 4; jj++)
                    acc[ii][jj] = ffma2(a2[ii], b2[jj], acc[ii][jj]);
        }
        __syncthreads();
    }
    #pragma unroll
    for (int ii = 0; ii < 4; ii++) {
        size_t r = bm + tr*4 + ii;
        int b = (int)(r >> 14), low = (int)(r & 16383);
        int t_, f_;
        if (stage == 0) { t_ = low >> 7; f_ = low & 127; }
        else            { f_ = low >> 7; t_ = low & 127; }
        #pragma unroll
        for (int jj = 0; jj < 4; jj++) {
            #pragma unroll
            for (int q = 0; q < 2; q++) {
                int n = tc*8 + jj*2 + q;
                float v = q ? acc[ii][jj].y : acc[ii][jj].x;
                size_t idx = (((size_t)(b*64 + n)*128) + t_)*128 + f_;
                xout[idx] = xin[idx] + v + fb[n];
            }
        }
    }
}

// ============================================================
extern "C" void kernel_launch(void* const* d_in, const int* in_sizes, int n_in,
                              void* d_out, int out_size)
{
    const float* x     = (const float*)d_in[0];
    const float* inW   = (const float*)d_in[1];
    const float* convW = (const float*)d_in[2];
    const float* convB = (const float*)d_in[3];
    const float* dtb   = (const float*)d_in[4];
    const float* Alog  = (const float*)d_in[5];
    const float* Dp    = (const float*)d_in[6];
    const float* nw    = (const float*)d_in[7];
    const float* outW  = (const float*)d_in[8];
    const float* fW    = (const float*)d_in[9];
    const float* fb    = (const float*)d_in[10];
    const float* lnw   = (const float*)d_in[11];
    const float* lnb   = (const float*)d_in[12];
    float* out = (float*)d_out;

    cudaFuncSetAttribute(ssd_kernel, cudaFuncAttributeMaxDynamicSharedMemorySize,
                         SSD_SMEM_BYTES);

    for (int st = 0; st < 2; st++) {
        int pf = 2*st, pb = 2*st + 1;
        ln_kernel<<<512, 256>>>(x, lnw + st*64, lnb + st*64, st);
        gemm_in<<<dim3(6, 512), 256>>>(inW + (size_t)pf*386*64, inW + (size_t)pb*386*64);
        dt_kernel<<<512, 256>>>(inW, dtb, Alog, pf, pb);
        ssd_kernel<<<1024, 512, SSD_SMEM_BYTES>>>(convW, convB, Dp, nw, pf, pb);
        wc_kernel<<<64, 256>>>(fW + st*64*128, outW, pf, pb);
        gemm_out<<<512, 256>>>(fb + st*64, x, out, st);
    }
}

// round 8
// speedup vs baseline: 1.6493x; 1.4095x over previous
#include <cuda_runtime.h>
#include <cuda_bf16.h>
#include <math.h>
#include <stdint.h>

#define S_ 512
#define L_ 128

// ---- packed f32x2 helpers ----
__device__ __forceinline__ float2 ffma2(float2 a, float2 b, float2 c) {
    unsigned long long ua = *reinterpret_cast<unsigned long long*>(&a);
    unsigned long long ub = *reinterpret_cast<unsigned long long*>(&b);
    unsigned long long uc = *reinterpret_cast<unsigned long long*>(&c);
    unsigned long long ud;
    asm("fma.rn.f32x2 %0, %1, %2, %3;" : "=l"(ud) : "l"(ua), "l"(ub), "l"(uc));
    return *reinterpret_cast<float2*>(&ud);
}
__device__ __forceinline__ float2 dup2(float a) {
    unsigned long long u;
    asm("mov.b64 %0, {%1, %1};" : "=l"(u) : "f"(a));
    return *reinterpret_cast<float2*>(&u);
}
__device__ __forceinline__ uint32_t bfpack(float a, float b) {
    return ((uint32_t)__bfloat16_as_ushort(__float2bfloat16_rn(b)) << 16)
         |  (uint32_t)__bfloat16_as_ushort(__float2bfloat16_rn(a));
}
__device__ __forceinline__ float bfres(float v) {
    return v - __bfloat162float(__float2bfloat16_rn(v));
}

// ---- scratch ----
__device__ __align__(16) float g_xwork[(size_t)4*64*128*128];
__device__ __align__(16) float g_u[(size_t)S_*L_*64];
__device__ __align__(16) uint32_t g_ub[(size_t)S_*L_*64];   // bf16x2: [row][hi 32 | lo 32]
__device__ __align__(16) uint32_t g_wb[2*384*64];           // bf16x2 per dir
__device__ __align__(16) float g_zx[2][(size_t)S_*L_*384];
__device__ __align__(16) float g_dt[2][(size_t)S_*L_*4];
__device__ __align__(16) float g_gbuf[(size_t)S_*L_*256];
__device__ __align__(16) float g_wc[64*256];

// ============================================================
// LayerNorm over channels + layout to (seq, pos, ch)
// ============================================================
__global__ void ln_kernel(const float* __restrict__ x_ext,
                          const float* __restrict__ lnw, const float* __restrict__ lnb,
                          int stage)
{
    __shared__ float tile[64][133];
    __shared__ float msh[128], rsh[128], wsh[64], bsh[64];
    const float* xin = stage ? g_xwork : x_ext;
    int bt = blockIdx.x, b = bt >> 7, t = bt & 127;
    int tid = threadIdx.x;
    if (tid < 64) { wsh[tid] = lnw[tid]; bsh[tid] = lnb[tid]; }
    const float* xb = xin + ((size_t)b*64*128 + t)*128;
    for (int i = tid; i < 8192; i += 256) {
        int c = i >> 7, f = i & 127;
        tile[c][f] = xb[(size_t)c*16384 + f];
    }
    __syncthreads();
    if (tid < 128) {
        float s = 0.f, ss = 0.f;
        #pragma unroll
        for (int c = 0; c < 64; c++) { float v = tile[c][tid]; s += v; ss += v*v; }
        float m = s * 0.015625f;
        msh[tid] = m;
        rsh[tid] = rsqrtf(ss * 0.015625f - m*m + 1e-5f);
    }
    __syncthreads();
    for (int i = tid; i < 8192; i += 256) {
        int f = i >> 6, c = i & 63;
        int row = stage ? ((b << 7) + f)*128 + t : ((b << 7) + t)*128 + f;
        g_u[(size_t)row*64 + c] = (tile[c][f] - msh[f]) * rsh[f] * wsh[c] + bsh[c];
    }
}

// ============================================================
// bf16-split conversions
// ============================================================
__global__ __launch_bounds__(256) void u_conv()
{
    int idx = blockIdx.x*256 + threadIdx.x;        // 1048576 threads
    float4 v = *(const float4*)&g_u[(size_t)idx*4];
    int row = idx >> 4, wo = (idx & 15)*2;
    uint32_t* o = g_ub + (size_t)row*64;
    uint2 hi = make_uint2(bfpack(v.x, v.y), bfpack(v.z, v.w));
    uint2 lo = make_uint2(bfpack(bfres(v.x), bfres(v.y)),
                          bfpack(bfres(v.z), bfres(v.w)));
    *(uint2*)&o[wo] = hi;
    *(uint2*)&o[32 + wo] = lo;
}

__global__ __launch_bounds__(256) void w_conv(const float* __restrict__ inW,
                                              int pf, int pb)
{
    int idx = blockIdx.x*256 + threadIdx.x;        // 12288 threads
    int d = idx >> 13, r = idx & 8191;             // 384*16 = 6144 < 8192
    if (r >= 6144) return;
    int n = r >> 4, wq = r & 15;
    int pidx = d ? pb : pf;
    float4 v = *(const float4*)&inW[(size_t)pidx*386*64 + n*64 + wq*4];
    uint32_t* o = g_wb + (size_t)(d*384 + n)*64;
    int wo = wq*2;
    *(uint2*)&o[wo]      = make_uint2(bfpack(v.x, v.y), bfpack(v.z, v.w));
    *(uint2*)&o[32 + wo] = make_uint2(bfpack(bfres(v.x), bfres(v.y)),
                                      bfpack(bfres(v.z), bfres(v.w)));
}

// ============================================================
// in_proj via tensor cores (bf16-split, 3 passes hi*hi + hi*lo + lo*hi).
// grid (6, 512): bx -> (dir, 128-col tile of 384), by -> 128-row tile.
// 256 thr = 8 warps, warp tile 32m x 64n, mma m16n8k16.
// ============================================================
#define GIN_SMEM_BYTES (2*128*68*4)
__global__ __launch_bounds__(256, 2) void gemm_in_mma()
{
    extern __shared__ uint32_t smw[];
    uint32_t* Asm = smw;              // [128][68]
    uint32_t* Bsm = smw + 128*68;     // [128][68]
    int bx = blockIdx.x;
    int dir = (bx >= 3);
    int j0 = (bx - dir*3) * 128;
    size_t bm = (size_t)blockIdx.y * 128;
    int tid = threadIdx.x;

    const uint4* gu = (const uint4*)&g_ub[bm*64];
    const uint4* gw = (const uint4*)&g_wb[(size_t)(dir*384 + j0)*64];
    #pragma unroll
    for (int t = 0; t < 8; t++) {
        int i = tid + t*256;
        int row = i >> 4, wq = i & 15;
        *(uint4*)&Asm[row*68 + wq*4] = gu[i];
        *(uint4*)&Bsm[row*68 + wq*4] = gw[i];
    }
    __syncthreads();

    int wid = tid >> 5, lane = tid & 31;
    int wm = wid & 3, wn = wid >> 2;
    int q = lane >> 2, w = lane & 3;
    uint32_t a_row = (wm*32 + q)*68;
    uint32_t b_row = (wn*64 + q)*68;

    float acc[2][8][4];
    #pragma unroll
    for (int mh = 0; mh < 2; mh++)
        #pragma unroll
        for (int tn = 0; tn < 8; tn++)
            #pragma unroll
            for (int r = 0; r < 4; r++) acc[mh][tn][r] = 0.f;

    #pragma unroll
    for (int c = 0; c < 3; c++) {
        int aoff = (c == 2) ? 32 : 0;
        int boff = (c == 1) ? 32 : 0;
        #pragma unroll
        for (int kc = 0; kc < 4; kc++) {
            int kb = kc*8 + w;
            uint32_t a0 = Asm[a_row + aoff + kb];
            uint32_t a1 = Asm[a_row + 8*68 + aoff + kb];
            uint32_t a2 = Asm[a_row + aoff + kb + 4];
            uint32_t a3 = Asm[a_row + 8*68 + aoff + kb + 4];
            uint32_t a4 = Asm[a_row + 16*68 + aoff + kb];
            uint32_t a5 = Asm[a_row + 24*68 + aoff + kb];
            uint32_t a6 = Asm[a_row + 16*68 + aoff + kb + 4];
            uint32_t a7 = Asm[a_row + 24*68 + aoff + kb + 4];
            #pragma unroll
            for (int tn = 0; tn < 8; tn++) {
                uint32_t b0 = Bsm[b_row + tn*8*68 + boff + kb];
                uint32_t b1 = Bsm[b_row + tn*8*68 + boff + kb + 4];
                asm volatile(
                    "mma.sync.aligned.m16n8k16.row.col.f32.bf16.bf16.f32 "
                    "{%0,%1,%2,%3}, {%4,%5,%6,%7}, {%8,%9}, {%0,%1,%2,%3};"
                    : "+f"(acc[0][tn][0]), "+f"(acc[0][tn][1]),
                      "+f"(acc[0][tn][2]), "+f"(acc[0][tn][3])
                    : "r"(a0), "r"(a1), "r"(a2), "r"(a3), "r"(b0), "r"(b1));
                asm volatile(
                    "mma.sync.aligned.m16n8k16.row.col.f32.bf16.bf16.f32 "
                    "{%0,%1,%2,%3}, {%4,%5,%6,%7}, {%8,%9}, {%0,%1,%2,%3};"
                    : "+f"(acc[1][tn][0]), "+f"(acc[1][tn][1]),
                      "+f"(acc[1][tn][2]), "+f"(acc[1][tn][3])
                    : "r"(a4), "r"(a5), "r"(a6), "r"(a7), "r"(b0), "r"(b1));
            }
        }
    }

    float* Cout = g_zx[dir];
    #pragma unroll
    for (int mh = 0; mh < 2; mh++) {
        #pragma unroll
        for (int tn = 0; tn < 8; tn++) {
            size_t m0 = bm + wm*32 + mh*16 + q;
            int col = j0 + wn*64 + tn*8 + w*2;
            *(float2*)&Cout[m0*384 + col] =
                make_float2(acc[mh][tn][0], acc[mh][tn][1]);
            *(float2*)&Cout[(m0+8)*384 + col] =
                make_float2(acc[mh][tn][2], acc[mh][tn][3]);
        }
    }
}

// ============================================================
// dt precompute: g_dt[dir][r] = {dt0, dt1, ldA0, ldA1}, ldA = -exp(Alog)*dt
// ============================================================
__global__ __launch_bounds__(256) void dt_kernel(const float* __restrict__ inW,
        const float* __restrict__ dtb, const float* __restrict__ Alog, int pf, int pb)
{
    __shared__ float usm[128][65];
    __shared__ float wsm[2][2][64];
    __shared__ float par[2][2][2];
    int tid = threadIdx.x;
    int r0 = blockIdx.x * 128;
    for (int i = tid; i < 8192; i += 256) {
        int m = i >> 6, k = i & 63;
        usm[m][k] = g_u[(size_t)(r0 + m)*64 + k];
    }
    {
        int d = tid >> 7, rest = tid & 127, h = rest >> 6, k = rest & 63;
        int pidx = d ? pb : pf;
        wsm[d][h][k] = inW[(size_t)pidx*386*64 + (384 + h)*64 + k];
    }
    if (tid < 4) {
        int d = tid >> 1, h = tid & 1;
        int pidx = d ? pb : pf;
        par[d][h][0] = dtb[pidx*2 + h];
        par[d][h][1] = -expf(Alog[pidx*2 + h]);
    }
    __syncthreads();
    int rl = tid & 127, d = tid >> 7;
    float out[4];
    #pragma unroll
    for (int h = 0; h < 2; h++) {
        float acc = 0.f;
        #pragma unroll
        for (int k = 0; k < 64; k++) acc = fmaf(usm[rl][k], wsm[d][h][k], acc);
        float xr = acc + par[d][h][0];
        float dt = (xr > 20.f) ? xr : log1pf(expf(xr));
        out[h] = dt;
        out[2 + h] = par[d][h][1] * dt;   // log dA
    }
    float* o = &g_dt[d][(size_t)(r0 + rl)*4];
    o[0] = out[0]; o[1] = out[1]; o[2] = out[2]; o[3] = out[3];
}

// ============================================================
// Fused SSD (R5 layout — best measured)
// ============================================================
#define SMX 0
#define SMBT 16896
#define SMCT 25344
#define SMG 33792
#define SMLL 50688
#define SMDT 50944
#define SSD_SMEM_FLOATS 51200
#define SSD_SMEM_BYTES (SSD_SMEM_FLOATS*4)

__global__ __launch_bounds__(512, 1) void ssd_kernel(
    const float* __restrict__ convW, const float* __restrict__ convB,
    const float* __restrict__ Dp, const float* __restrict__ normw, int pf, int pb)
{
    extern __shared__ float sm[];
    int blk = blockIdx.x, dir = blk >> 9, s = blk & 511;
    int pidx = dir ? pb : pf;
    int tid = threadIdx.x;
    const float* zxa = g_zx[dir] + (size_t)s * L_ * 384;

    {
        int ch = tid & 255, hf = tid >> 8;
        float cw0 = convW[pidx*1024 + ch*4 + 0];
        float cw1 = convW[pidx*1024 + ch*4 + 1];
        float cw2 = convW[pidx*1024 + ch*4 + 2];
        float cw3 = convW[pidx*1024 + ch*4 + 3];
        float cb  = convB[pidx*256 + ch];
        const float* src = zxa + 128 + ch;
        float* obase;
        int ostep;
        if (ch < 128)      { obase = sm + SMX + ch;              ostep = 132; }
        else if (ch < 192) { obase = sm + SMBT + (ch-128)*132;   ostep = 1;   }
        else               { obase = sm + SMCT + (ch-192)*132;   ostep = 1;   }
        int ls = hf * 64;
        float xm3 = 0.f, xm2 = 0.f, xm1 = 0.f;
        #pragma unroll
        for (int j = 0; j < 3; j++) {
            int l = ls - 3 + j;
            float v = 0.f;
            if (l >= 0) v = src[(size_t)(dir ? 127-l : l)*384];
            xm3 = xm2; xm2 = xm1; xm1 = v;
        }
        float nxt[4];
        #pragma unroll
        for (int j = 0; j < 4; j++)
            nxt[j] = src[(size_t)(dir ? 127-(ls+j) : (ls+j))*384];
        for (int lb = 0; lb < 64; lb += 4) {
            float cur[4];
            #pragma unroll
            for (int j = 0; j < 4; j++) cur[j] = nxt[j];
            if (lb + 4 < 64) {
                #pragma unroll
                for (int j = 0; j < 4; j++) {
                    int l = ls + lb + 4 + j;
                    nxt[j] = src[(size_t)(dir ? 127-l : l)*384];
                }
            }
            #pragma unroll
            for (int j = 0; j < 4; j++) {
                float v = cur[j];
                float acc = cb;
                acc = fmaf(cw0, xm3, acc);
                acc = fmaf(cw1, xm2, acc);
                acc = fmaf(cw2, xm1, acc);
                acc = fmaf(cw3, v,   acc);
                xm3 = xm2; xm2 = xm1; xm1 = v;
                float y = acc / (1.f + expf(-acc));
                obase[(ls + lb + j) * ostep] = y;
            }
        }
    }
    if (tid < 64) {
        int h = tid >> 5, lane = tid & 31;
        float carry = 0.f;
        for (int c = 0; c < 4; c++) {
            int l = c*32 + lane;
            int lp = dir ? 127 - l : l;
            const float* dr = g_dt[dir] + ((size_t)s*128 + lp)*4;
            sm[SMDT + h*128 + l] = dr[h];
            float v = dr[2 + h];
            #pragma unroll
            for (int o = 1; o < 32; o <<= 1) {
                float t = __shfl_up_sync(0xffffffffu, v, o);
                if (lane >= o) v += t;
            }
            sm[SMLL + h*128 + l] = v + carry;
            carry += __shfl_sync(0xffffffffu, v, 31);
        }
    }
    __syncthreads();

    int ti = tid >> 4;
    int pi = tid & 15;
    int t0 = ti * 4;
    float2 accY[2][4][2];
    #pragma unroll
    for (int h = 0; h < 2; h++)
        #pragma unroll
        for (int i = 0; i < 4; i++) {
            accY[h][i][0] = make_float2(0.f, 0.f);
            accY[h][i][1] = make_float2(0.f, 0.f);
        }

    #pragma unroll
    for (int p = 0; p < 2; p++) {
        int s_base = p * 64;
        int s0 = s_base + pi * 4;
        float2 pacc[4][2];
        #pragma unroll
        for (int i = 0; i < 4; i++) {
            pacc[i][0] = make_float2(0.f, 0.f);
            pacc[i][1] = make_float2(0.f, 0.f);
        }
        if (s0 <= t0 + 3) {
            #pragma unroll 4
            for (int n = 0; n < 64; n++) {
                float4 c4 = *(const float4*)&sm[SMCT + n*132 + t0];
                float4 b4 = *(const float4*)&sm[SMBT + n*132 + s0];
                float a[4] = {c4.x, c4.y, c4.z, c4.w};
                float2 bb[2] = {{b4.x, b4.y}, {b4.z, b4.w}};
                #pragma unroll
                for (int i = 0; i < 4; i++) {
                    float2 aa = dup2(a[i]);
                    pacc[i][0] = ffma2(aa, bb[0], pacc[i][0]);
                    pacc[i][1] = ffma2(aa, bb[1], pacc[i][1]);
                }
            }
        }
        #pragma unroll
        for (int h = 0; h < 2; h++) {
            float llt[4];
            #pragma unroll
            for (int i = 0; i < 4; i++) llt[i] = sm[SMLL + h*128 + t0 + i];
            #pragma unroll
            for (int j = 0; j < 4; j++) {
                int sg = s0 + j;
                float dts = sm[SMDT + h*128 + sg];
                float lls = sm[SMLL + h*128 + sg];
                float pv[4];
                #pragma unroll
                for (int i = 0; i < 4; i++)
                    pv[i] = (j & 1) ? pacc[i][j>>1].y : pacc[i][j>>1].x;
                float4 g4;
                g4.x = (sg <= t0+0) ? pv[0]*dts*__expf(llt[0]-lls) : 0.f;
                g4.y = (sg <= t0+1) ? pv[1]*dts*__expf(llt[1]-lls) : 0.f;
                g4.z = (sg <= t0+2) ? pv[2]*dts*__expf(llt[2]-lls) : 0.f;
                g4.w = (sg <= t0+3) ? pv[3]*dts*__expf(llt[3]-lls) : 0.f;
                *(float4*)&sm[SMG + (h*64 + sg - s_base)*132 + t0] = g4;
            }
        }
        __syncthreads();
        int klim = t0 + 4 - s_base;
        if (klim > 64) klim = 64;
        for (int sl = 0; sl < klim; sl++) {
            int sg = s_base + sl;
            float4 g0 = *(const float4*)&sm[SMG + sl*132 + t0];
            float4 g1 = *(const float4*)&sm[SMG + (64 + sl)*132 + t0];
            float4 x0 = *(const float4*)&sm[SMX + sg*132 + pi*4];
            float4 x1 = *(const float4*)&sm[SMX + sg*132 + 64 + pi*4];
            float2 b00 = {x0.x, x0.y}, b01 = {x0.z, x0.w};
            float2 b10 = {x1.x, x1.y}, b11 = {x1.z, x1.w};
            float ga0[4] = {g0.x, g0.y, g0.z, g0.w};
            float ga1[4] = {g1.x, g1.y, g1.z, g1.w};
            #pragma unroll
            for (int i = 0; i < 4; i++) {
                float2 a0 = dup2(ga0[i]);
                float2 a1 = dup2(ga1[i]);
                accY[0][i][0] = ffma2(a0, b00, accY[0][i][0]);
                accY[0][i][1] = ffma2(a0, b01, accY[0][i][1]);
                accY[1][i][0] = ffma2(a1, b10, accY[1][i][0]);
                accY[1][i][1] = ffma2(a1, b11, accY[1][i][1]);
            }
        }
        __syncthreads();
    }

    {
        float Dv0 = Dp[pidx*2], Dv1 = Dp[pidx*2 + 1];
        float4 nw0 = *(const float4*)&normw[pidx*128 + pi*4];
        float4 nw1 = *(const float4*)&normw[pidx*128 + 64 + pi*4];
        #pragma unroll
        for (int i = 0; i < 4; i++) {
            int l = t0 + i;
            int lp = dir ? 127 - l : l;
            float4 x0 = *(const float4*)&sm[SMX + l*132 + pi*4];
            float4 x1 = *(const float4*)&sm[SMX + l*132 + 64 + pi*4];
            const float* zr = zxa + (size_t)lp*384;
            float4 z0 = *(const float4*)&zr[pi*4];
            float4 z1 = *(const float4*)&zr[64 + pi*4];
            float g[8];
            g[0] = fmaf(Dv0, x0.x, accY[0][i][0].x);
            g[1] = fmaf(Dv0, x0.y, accY[0][i][0].y);
            g[2] = fmaf(Dv0, x0.z, accY[0][i][1].x);
            g[3] = fmaf(Dv0, x0.w, accY[0][i][1].y);
            g[4] = fmaf(Dv1, x1.x, accY[1][i][0].x);
            g[5] = fmaf(Dv1, x1.y, accY[1][i][0].y);
            g[6] = fmaf(Dv1, x1.z, accY[1][i][1].x);
            g[7] = fmaf(Dv1, x1.w, accY[1][i][1].y);
            float z[8] = {z0.x, z0.y, z0.z, z0.w, z1.x, z1.y, z1.z, z1.w};
            float ss = 0.f;
            #pragma unroll
            for (int j = 0; j < 8; j++) {
                g[j] = g[j] * (z[j] / (1.f + expf(-z[j])));
                ss = fmaf(g[j], g[j], ss);
            }
            ss += __shfl_xor_sync(0xffffffffu, ss, 1);
            ss += __shfl_xor_sync(0xffffffffu, ss, 2);
            ss += __shfl_xor_sync(0xffffffffu, ss, 4);
            ss += __shfl_xor_sync(0xffffffffu, ss, 8);
            float rs = rsqrtf(ss * 0.0078125f + 1e-5f);
            float* go = g_gbuf + ((size_t)s*128 + lp)*256 + (dir << 7);
            *(float4*)&go[pi*4]      = make_float4(g[0]*rs*nw0.x, g[1]*rs*nw0.y,
                                                   g[2]*rs*nw0.z, g[3]*rs*nw0.w);
            *(float4*)&go[64 + pi*4] = make_float4(g[4]*rs*nw1.x, g[5]*rs*nw1.y,
                                                   g[6]*rs*nw1.z, g[7]*rs*nw1.w);
        }
    }
}

// ============================================================
// Fold out_proj x fusion
// ============================================================
__global__ void wc_kernel(const float* __restrict__ fW, const float* __restrict__ oW,
                          int pf, int pb)
{
    int idx = blockIdx.x*256 + threadIdx.x;
    int m = idx >> 8, r = idx & 255, dir = r >> 7, j = r & 127;
    int pidx = dir ? pb : pf;
    const float* wo = oW + (size_t)pidx*64*128;
    const float* wf = fW + m*128 + (dir << 6);
    float acc = 0.f;
    #pragma unroll
    for (int i = 0; i < 64; i++) acc = fmaf(wf[i], wo[i*128 + j], acc);
    g_wc[idx] = acc;
}

// ============================================================
// final GEMM + residual + scatter (R5 version). M=65536, N=64, K=256.
// ============================================================
__global__ __launch_bounds__(256) void gemm_out(const float* __restrict__ fb,
        const float* __restrict__ x_ext, float* __restrict__ out_ext, int stage)
{
    __shared__ __align__(16) float As[16][68];
    __shared__ __align__(16) float Ws[16][68];
    const float* xin = stage ? g_xwork : x_ext;
    float* xout = stage ? out_ext : g_xwork;
    size_t bm = (size_t)blockIdx.x * 64;
    int tid = threadIdx.x, tr = tid >> 4, tc = tid & 15;
    float acc[4][4] = {};
    for (int k0 = 0; k0 < 256; k0 += 16) {
        #pragma unroll
        for (int i = tid; i < 1024; i += 256) {
            int m = i >> 4, k = i & 15;
            As[k][m] = g_gbuf[(bm + m)*256 + k0 + k];
        }
        #pragma unroll
        for (int i = tid; i < 1024; i += 256) {
            int n = i >> 4, k = i & 15;
            Ws[k][n] = g_wc[n*256 + k0 + k];
        }
        __syncthreads();
        #pragma unroll
        for (int k = 0; k < 16; k++) {
            float a[4], b4[4];
            *(float4*)a  = *(const float4*)&As[k][tr*4];
            *(float4*)b4 = *(const float4*)&Ws[k][tc*4];
            #pragma unroll
            for (int ii = 0; ii < 4; ii++)
                #pragma unroll
                for (int jj = 0; jj < 4; jj++)
                    acc[ii][jj] = fmaf(a[ii], b4[jj], acc[ii][jj]);
        }
        __syncthreads();
    }
    #pragma unroll
    for (int ii = 0; ii < 4; ii++) {
        size_t r = bm + tr*4 + ii;
        int b = (int)(r >> 14), low = (int)(r & 16383);
        int t_, f_;
        if (stage == 0) { t_ = low >> 7; f_ = low & 127; }
        else            { f_ = low >> 7; t_ = low & 127; }
        #pragma unroll
        for (int jj = 0; jj < 4; jj++) {
            int n = tc*4 + jj;
            size_t idx = (((size_t)(b*64 + n)*128) + t_)*128 + f_;
            xout[idx] = xin[idx] + acc[ii][jj] + fb[n];
        }
    }
}

// ============================================================
extern "C" void kernel_launch(void* const* d_in, const int* in_sizes, int n_in,
                              void* d_out, int out_size)
{
    const float* x     = (const float*)d_in[0];
    const float* inW   = (const float*)d_in[1];
    const float* convW = (const float*)d_in[2];
    const float* convB = (const float*)d_in[3];
    const float* dtb   = (const float*)d_in[4];
    const float* Alog  = (const float*)d_in[5];
    const float* Dp    = (const float*)d_in[6];
    const float* nw    = (const float*)d_in[7];
    const float* outW  = (const float*)d_in[8];
    const float* fW    = (const float*)d_in[9];
    const float* fb    = (const float*)d_in[10];
    const float* lnw   = (const float*)d_in[11];
    const float* lnb   = (const float*)d_in[12];
    float* out = (float*)d_out;

    cudaFuncSetAttribute(ssd_kernel, cudaFuncAttributeMaxDynamicSharedMemorySize,
                         SSD_SMEM_BYTES);
    cudaFuncSetAttribute(gemm_in_mma, cudaFuncAttributeMaxDynamicSharedMemorySize,
                         GIN_SMEM_BYTES);

    for (int st = 0; st < 2; st++) {
        int pf = 2*st, pb = 2*st + 1;
        ln_kernel<<<512, 256>>>(x, lnw + st*64, lnb + st*64, st);
        u_conv<<<4096, 256>>>();
        w_conv<<<64, 256>>>(inW, pf, pb);
        gemm_in_mma<<<dim3(6, 512), 256, GIN_SMEM_BYTES>>>();
        dt_kernel<<<512, 256>>>(inW, dtb, Alog, pf, pb);
        ssd_kernel<<<1024, 512, SSD_SMEM_BYTES>>>(convW, convB, Dp, nw, pf, pb);
        wc_kernel<<<64, 256>>>(fW + st*64*128, outW, pf, pb);
        gemm_out<<<1024, 256>>>(fb + st*64, x, out, st);
    }
}